// round 2
// baseline (speedup 1.0000x reference)
#include <cuda_runtime.h>
#include <cuda_bf16.h>
#include <cstddef>

// Problem constants
#define Hh   512
#define INPS 2048
#define FS   1536
#define Bb   128
#define Tt   64
#define MROWS (Bb * Tt)          // 8192

// Scratch for precomputed projections (device statics: allocation-free)
__device__ float g_gi[(size_t)MROWS * (3 * Hh)];   // [B*T, 1536]
__device__ float g_gf[(size_t)MROWS * (2 * Hh)];   // [B*T, 1024]

// ---------------------------------------------------------------------------
// SGEMM: C[M,N] = A[M,K] * W[N,K]^T + bias[N]
// BM=BN=128, BK=16, TM=TN=8, 256 threads. All dims divisible by tiles here.
// ---------------------------------------------------------------------------
__global__ __launch_bounds__(256, 2)
void sgemm_bias_kernel(const float* __restrict__ A,
                       const float* __restrict__ W,
                       const float* __restrict__ bias,
                       float* __restrict__ C,
                       int M, int N, int K)
{
    constexpr int BM = 128, BN = 128, BK = 16, TM = 8, TN = 8;
    __shared__ float As[BK][BM];
    __shared__ float Ws[BK][BN];

    const int tid  = threadIdx.x;
    const int bm   = blockIdx.y;
    const int bn   = blockIdx.x;
    const int tcol = tid % (BN / TN);   // 0..15
    const int trow = tid / (BN / TN);   // 0..15

    const float* Ablk = A + (size_t)bm * BM * K;
    const float* Wblk = W + (size_t)bn * BN * K;

    float acc[TM][TN];
#pragma unroll
    for (int i = 0; i < TM; i++)
#pragma unroll
        for (int j = 0; j < TN; j++) acc[i][j] = 0.0f;

    for (int k0 = 0; k0 < K; k0 += BK) {
        // Load A tile (128x16) as float4: 512 float4 / 256 threads = 2 each
#pragma unroll
        for (int i = 0; i < 2; i++) {
            int idx = tid + i * 256;              // 0..511
            int row = idx >> 2;                   // /4 (BK/4 = 4 float4 per row)
            int kq  = idx & 3;
            float4 v = *(const float4*)(Ablk + (size_t)row * K + k0 + kq * 4);
            As[kq * 4 + 0][row] = v.x;
            As[kq * 4 + 1][row] = v.y;
            As[kq * 4 + 2][row] = v.z;
            As[kq * 4 + 3][row] = v.w;
        }
#pragma unroll
        for (int i = 0; i < 2; i++) {
            int idx = tid + i * 256;
            int row = idx >> 2;
            int kq  = idx & 3;
            float4 v = *(const float4*)(Wblk + (size_t)row * K + k0 + kq * 4);
            Ws[kq * 4 + 0][row] = v.x;
            Ws[kq * 4 + 1][row] = v.y;
            Ws[kq * 4 + 2][row] = v.z;
            Ws[kq * 4 + 3][row] = v.w;
        }
        __syncthreads();

#pragma unroll
        for (int k = 0; k < BK; k++) {
            float ra[TM], rb[TN];
            const float4* a4 = reinterpret_cast<const float4*>(&As[k][trow * TM]);
            const float4* b4 = reinterpret_cast<const float4*>(&Ws[k][tcol * TN]);
            float4 av0 = a4[0], av1 = a4[1];
            float4 bv0 = b4[0], bv1 = b4[1];
            ra[0]=av0.x; ra[1]=av0.y; ra[2]=av0.z; ra[3]=av0.w;
            ra[4]=av1.x; ra[5]=av1.y; ra[6]=av1.z; ra[7]=av1.w;
            rb[0]=bv0.x; rb[1]=bv0.y; rb[2]=bv0.z; rb[3]=bv0.w;
            rb[4]=bv1.x; rb[5]=bv1.y; rb[6]=bv1.z; rb[7]=bv1.w;
#pragma unroll
            for (int i = 0; i < TM; i++)
#pragma unroll
                for (int j = 0; j < TN; j++)
                    acc[i][j] = fmaf(ra[i], rb[j], acc[i][j]);
        }
        __syncthreads();
    }

    // Epilogue: bias + store
    const int crow0 = bm * BM + trow * TM;
    const int ccol0 = bn * BN + tcol * TN;
#pragma unroll
    for (int i = 0; i < TM; i++) {
        float* crow = C + (size_t)(crow0 + i) * N + ccol0;
#pragma unroll
        for (int j = 0; j < TN; j++)
            crow[j] = acc[i][j] + bias[ccol0 + j];
    }
}

// ---------------------------------------------------------------------------
// Fused recurrent step: for timestep t, compute
//   gh[b, g*512+n] = sum_k h_{t-1}[b,k] * W_hh[g*512+n, k] + b_hh[g*512+n]
//   gates + h_t.  h_{t-1} read from out[:, t-1, :]; h_t written to out[:, t, :].
// Block tile: 16 batch rows x 64 h-cols, all 3 gates. 256 threads.
// Thread: c = tid%64 (col), rg = tid/64 -> rows rg*4 .. rg*4+3.
// ---------------------------------------------------------------------------
__global__ __launch_bounds__(256, 4)
void gru_step_kernel(const float* __restrict__ gi,     // [B*T, 1536]
                     const float* __restrict__ gf,     // [B*T, 1024]
                     const float* __restrict__ W_hh,   // [1536, 512]
                     const float* __restrict__ b_hh,   // [1536]
                     float* __restrict__ out,          // eo [B,T,H] then hT [B,H]
                     int t)
{
    constexpr int BR = 16, BC = 64, KC = 32;
    __shared__ float h_sm[BR][KC];
    __shared__ float W_sm[3][KC][BC + 1];   // +1 pad: conflict-free k-strided stores

    const int tid  = threadIdx.x;
    const int c    = tid & 63;        // 0..63 column within tile
    const int rg   = tid >> 6;        // 0..3 row group
    const int lane = tid & 31;
    const int warp = tid >> 5;        // 0..7

    const int colBase = blockIdx.x * BC;   // 0..448
    const int rowBase = blockIdx.y * BR;   // 0..112

    float acc[3][4];
#pragma unroll
    for (int g = 0; g < 3; g++)
#pragma unroll
        for (int j = 0; j < 4; j++) acc[g][j] = 0.0f;

    const size_t prevBase = (size_t)(t - 1) * Hh;   // within a batch row of eo

    for (int k0 = 0; k0 < Hh; k0 += KC) {
        // Load h tile: 16 rows x 32 k (512 elems / 256 threads = 2 each)
#pragma unroll
        for (int i = 0; i < 2; i++) {
            int idx = tid + i * 256;
            int r   = idx >> 5;       // /32
            int k   = idx & 31;
            float v = 0.0f;
            if (t > 0) {
                int b = rowBase + r;
                v = out[(size_t)b * (Tt * Hh) + prevBase + k0 + k];
            }
            h_sm[r][k] = v;
        }
        // Load W tiles: 3 gates x 64 cols x 32 k = 192 rows of 32.
        // warp w handles rows w, w+8, ..., w+184 (24 rows), lane = k.
#pragma unroll
        for (int i = 0; i < 24; i++) {
            int row = warp + i * 8;       // 0..191
            int g   = row >> 6;           // /64
            int cc  = row & 63;
            float v = W_hh[(size_t)(g * Hh + colBase + cc) * Hh + k0 + lane];
            W_sm[g][lane][cc] = v;
        }
        __syncthreads();

#pragma unroll
        for (int k = 0; k < KC; k++) {
            float hv0 = h_sm[rg * 4 + 0][k];
            float hv1 = h_sm[rg * 4 + 1][k];
            float hv2 = h_sm[rg * 4 + 2][k];
            float hv3 = h_sm[rg * 4 + 3][k];
#pragma unroll
            for (int g = 0; g < 3; g++) {
                float wv = W_sm[g][k][c];
                acc[g][0] = fmaf(hv0, wv, acc[g][0]);
                acc[g][1] = fmaf(hv1, wv, acc[g][1]);
                acc[g][2] = fmaf(hv2, wv, acc[g][2]);
                acc[g][3] = fmaf(hv3, wv, acc[g][3]);
            }
        }
        __syncthreads();
    }

    // Gates + update
    const int n = colBase + c;
    const float bhr = b_hh[n];
    const float bhi = b_hh[Hh + n];
    const float bhn = b_hh[2 * Hh + n];

#pragma unroll
    for (int j = 0; j < 4; j++) {
        const int b = rowBase + rg * 4 + j;
        const size_t gib = (size_t)(b * Tt + t) * (3 * Hh);
        const size_t gfb = (size_t)(b * Tt + t) * (2 * Hh);

        float ghr = acc[0][j] + bhr;
        float ghi = acc[1][j] + bhi;
        float ghn = acc[2][j] + bhn;

        float xr = gi[gib + n]           + ghr + gf[gfb + n];
        float xi = gi[gib + Hh + n]      + ghi + gf[gfb + Hh + n];
        float resetgate = 1.0f / (1.0f + expf(-xr));
        float inputgate = 1.0f / (1.0f + expf(-xi));
        float newgate   = tanhf(gi[gib + 2 * Hh + n] + resetgate * ghn);

        float hprev = 0.0f;
        if (t > 0) hprev = out[(size_t)b * (Tt * Hh) + prevBase + n];
        float hy = newgate + inputgate * (hprev - newgate);

        out[(size_t)b * (Tt * Hh) + (size_t)t * Hh + n] = hy;
        if (t == Tt - 1)
            out[(size_t)Bb * Tt * Hh + (size_t)b * Hh + n] = hy;
    }
}

// ---------------------------------------------------------------------------
// Launch
// ---------------------------------------------------------------------------
extern "C" void kernel_launch(void* const* d_in, const int* in_sizes, int n_in,
                              void* d_out, int out_size)
{
    const float* feat0 = (const float*)d_in[0];   // [B,T,FS]
    const float* feat1 = (const float*)d_in[1];   // [B,T,IN]
    const float* W_ih  = (const float*)d_in[2];   // [3H, IN]
    const float* b_ih  = (const float*)d_in[3];   // [3H]
    const float* W_hh  = (const float*)d_in[4];   // [3H, H]
    const float* b_hh  = (const float*)d_in[5];   // [3H]
    const float* W_fh  = (const float*)d_in[6];   // [2H, FS]
    const float* b_fh  = (const float*)d_in[7];   // [2H]
    float* out = (float*)d_out;

    float *gi_ptr, *gf_ptr;
    cudaGetSymbolAddress((void**)&gi_ptr, g_gi);
    cudaGetSymbolAddress((void**)&gf_ptr, g_gf);

    // gi = feat1 @ W_ih^T + b_ih : M=8192, N=1536, K=2048
    {
        dim3 grid((3 * Hh) / 128, MROWS / 128);
        sgemm_bias_kernel<<<grid, 256>>>(feat1, W_ih, b_ih, gi_ptr,
                                         MROWS, 3 * Hh, INPS);
    }
    // gf = feat0 @ W_fh^T + b_fh : M=8192, N=1024, K=1536
    {
        dim3 grid((2 * Hh) / 128, MROWS / 128);
        sgemm_bias_kernel<<<grid, 256>>>(feat0, W_fh, b_fh, gf_ptr,
                                         MROWS, 2 * Hh, FS);
    }
    // Recurrence: 64 sequential fused steps
    {
        dim3 grid(Hh / 64, Bb / 16);   // (8, 8)
        for (int t = 0; t < Tt; t++)
            gru_step_kernel<<<grid, 256>>>(gi_ptr, gf_ptr, W_hh, b_hh, out, t);
    }
}

// round 3
// speedup vs baseline: 1.3682x; 1.3682x over previous
#include <cuda_runtime.h>
#include <cuda_bf16.h>
#include <cstddef>

// Problem constants
#define Hh   512
#define INPS 2048
#define FS   1536
#define Bb   128
#define Tt   64
#define MROWS (Bb * Tt)          // 8192

// Persistent-recurrence tiling
#define NC   16                  // hidden cols per CTA
#define BBB  32                  // batch rows per CTA
#define NBLK 128                 // total CTAs (32 col-chunks x 4 batch-chunks)
#define STEP_THREADS 256

// Scratch for precomputed projections (device statics: allocation-free)
__device__ float g_gi[(size_t)MROWS * (3 * Hh)];   // [B*T, 1536]
__device__ float g_gf[(size_t)MROWS * (2 * Hh)];   // [B*T, 1024]
__device__ unsigned int g_bar;                      // grid-barrier counter (monotone)

// ---------------------------------------------------------------------------
// SGEMM: C[M,N] = A[M,K] * W[N,K]^T + bias[N]
// BM=BN=128, BK=16, TM=TN=8, 256 threads. All dims divisible by tiles here.
// ---------------------------------------------------------------------------
__global__ __launch_bounds__(256, 2)
void sgemm_bias_kernel(const float* __restrict__ A,
                       const float* __restrict__ W,
                       const float* __restrict__ bias,
                       float* __restrict__ C,
                       int M, int N, int K)
{
    constexpr int BM = 128, BN = 128, BK = 16, TM = 8, TN = 8;
    __shared__ float As[BK][BM];
    __shared__ float Ws[BK][BN];

    const int tid  = threadIdx.x;
    const int bm   = blockIdx.y;
    const int bn   = blockIdx.x;
    const int tcol = tid % (BN / TN);   // 0..15
    const int trow = tid / (BN / TN);   // 0..15

    const float* Ablk = A + (size_t)bm * BM * K;
    const float* Wblk = W + (size_t)bn * BN * K;

    float acc[TM][TN];
#pragma unroll
    for (int i = 0; i < TM; i++)
#pragma unroll
        for (int j = 0; j < TN; j++) acc[i][j] = 0.0f;

    for (int k0 = 0; k0 < K; k0 += BK) {
#pragma unroll
        for (int i = 0; i < 2; i++) {
            int idx = tid + i * 256;              // 0..511
            int row = idx >> 2;
            int kq  = idx & 3;
            float4 v = *(const float4*)(Ablk + (size_t)row * K + k0 + kq * 4);
            As[kq * 4 + 0][row] = v.x;
            As[kq * 4 + 1][row] = v.y;
            As[kq * 4 + 2][row] = v.z;
            As[kq * 4 + 3][row] = v.w;
        }
#pragma unroll
        for (int i = 0; i < 2; i++) {
            int idx = tid + i * 256;
            int row = idx >> 2;
            int kq  = idx & 3;
            float4 v = *(const float4*)(Wblk + (size_t)row * K + k0 + kq * 4);
            Ws[kq * 4 + 0][row] = v.x;
            Ws[kq * 4 + 1][row] = v.y;
            Ws[kq * 4 + 2][row] = v.z;
            Ws[kq * 4 + 3][row] = v.w;
        }
        __syncthreads();

#pragma unroll
        for (int k = 0; k < BK; k++) {
            float ra[TM], rb[TN];
            const float4* a4 = reinterpret_cast<const float4*>(&As[k][trow * TM]);
            const float4* b4 = reinterpret_cast<const float4*>(&Ws[k][tcol * TN]);
            float4 av0 = a4[0], av1 = a4[1];
            float4 bv0 = b4[0], bv1 = b4[1];
            ra[0]=av0.x; ra[1]=av0.y; ra[2]=av0.z; ra[3]=av0.w;
            ra[4]=av1.x; ra[5]=av1.y; ra[6]=av1.z; ra[7]=av1.w;
            rb[0]=bv0.x; rb[1]=bv0.y; rb[2]=bv0.z; rb[3]=bv0.w;
            rb[4]=bv1.x; rb[5]=bv1.y; rb[6]=bv1.z; rb[7]=bv1.w;
#pragma unroll
            for (int i = 0; i < TM; i++)
#pragma unroll
                for (int j = 0; j < TN; j++)
                    acc[i][j] = fmaf(ra[i], rb[j], acc[i][j]);
        }
        __syncthreads();
    }

    const int crow0 = bm * BM + trow * TM;
    const int ccol0 = bn * BN + tcol * TN;
#pragma unroll
    for (int i = 0; i < TM; i++) {
        float* crow = C + (size_t)(crow0 + i) * N + ccol0;
#pragma unroll
        for (int j = 0; j < TN; j++)
            crow[j] = acc[i][j] + bias[ccol0 + j];
    }
}

// ---------------------------------------------------------------------------
// Persistent GRU recurrence: ONE kernel runs all 64 timesteps.
// 128 CTAs (32 col-chunks x 4 batch-chunks), all co-resident (1/SM at 160KB smem).
// W_hh slice lives in smem for the whole kernel. Software grid barrier per step.
// Thread map: c = tid&15 (col within chunk), bg = tid>>4 (0..15) -> 2 batches.
// Register tile: 3 gates x 2 batches = 6 accumulators.
// ---------------------------------------------------------------------------
__global__ __launch_bounds__(STEP_THREADS, 1)
void gru_persistent_kernel(const float* __restrict__ gi,     // [B*T, 1536]
                           const float* __restrict__ gf,     // [B*T, 1024]
                           const float* __restrict__ W_hh,   // [1536, 512]
                           const float* __restrict__ b_hh,   // [1536]
                           float* __restrict__ out)          // eo [B,T,H] then hT [B,H]
{
    extern __shared__ float sm[];
    float* W_sm = sm;                        // [3][512][NC]  (k-major rows of NC cols)
    float* h_sm = sm + 3 * Hh * NC;          // [BBB][512]

    const int tid = threadIdx.x;
    const int c   = tid & (NC - 1);          // 0..15
    const int bg  = tid >> 4;                // 0..15
    const int colBase = blockIdx.x * NC;     // 0..496
    const int bBase   = blockIdx.y * BBB;    // 0..96
    const int n = colBase + c;

    // ---- One-time: stage W_hh slice (3 gates x NC cols x 512 k) into smem ----
    // Layout: W_sm[((g*512)+k)*NC + cc]  -> compute reads 16 consecutive floats.
    for (int i = tid; i < 3 * NC * (Hh / 4); i += STEP_THREADS) {
        int r  = i >> 7;          // row 0..(3*NC-1): g*NC + cc
        int kq = i & 127;         // float4 index over k
        int g  = r / NC;
        int cc = r - g * NC;
        float4 v = *(const float4*)(W_hh + (size_t)(g * Hh + colBase + cc) * Hh + kq * 4);
        int k = kq * 4;
        W_sm[((g * Hh) + k + 0) * NC + cc] = v.x;
        W_sm[((g * Hh) + k + 1) * NC + cc] = v.y;
        W_sm[((g * Hh) + k + 2) * NC + cc] = v.z;
        W_sm[((g * Hh) + k + 3) * NC + cc] = v.w;
    }

    const float bhr = b_hh[n];
    const float bhi = b_hh[Hh + n];
    const float bhn = b_hh[2 * Hh + n];

    for (int t = 0; t < Tt; t++) {
        // ---- Stage h_{t-1}[bBase..bBase+31, :] into smem ----
        if (t == 0) {
            float4 z = make_float4(0.f, 0.f, 0.f, 0.f);
            for (int i = tid; i < BBB * (Hh / 4); i += STEP_THREADS)
                *(float4*)(h_sm + i * 4) = z;
        } else {
            for (int i = tid; i < BBB * (Hh / 4); i += STEP_THREADS) {
                int bl = i >> 7;           // local batch
                int kq = i & 127;
                float4 v = *(const float4*)(out +
                    ((size_t)(bBase + bl) * Tt + (t - 1)) * Hh + kq * 4);
                *(float4*)(h_sm + bl * Hh + kq * 4) = v;
            }
        }
        __syncthreads();

        // ---- gh = h_{t-1} @ W_hh^T for this (batch,col) tile ----
        float a00 = 0.f, a01 = 0.f;   // gate r, batches j=0,1
        float a10 = 0.f, a11 = 0.f;   // gate i
        float a20 = 0.f, a21 = 0.f;   // gate n
        const float* h0p = h_sm + (bg * 2 + 0) * Hh;
        const float* h1p = h_sm + (bg * 2 + 1) * Hh;
        const float* w0p = W_sm + (0 * Hh) * NC + c;
        const float* w1p = W_sm + (1 * Hh) * NC + c;
        const float* w2p = W_sm + (2 * Hh) * NC + c;
#pragma unroll 8
        for (int k = 0; k < Hh; k++) {
            float h0 = h0p[k];
            float h1 = h1p[k];
            float w0 = w0p[k * NC];
            float w1 = w1p[k * NC];
            float w2 = w2p[k * NC];
            a00 = fmaf(w0, h0, a00);  a01 = fmaf(w0, h1, a01);
            a10 = fmaf(w1, h0, a10);  a11 = fmaf(w1, h1, a11);
            a20 = fmaf(w2, h0, a20);  a21 = fmaf(w2, h1, a21);
        }

        // ---- Gates + state update ----
#pragma unroll
        for (int j = 0; j < 2; j++) {
            const int b = bBase + bg * 2 + j;
            const size_t gib = ((size_t)b * Tt + t) * (3 * Hh);
            const size_t gfb = ((size_t)b * Tt + t) * (2 * Hh);

            float ghr = (j ? a01 : a00) + bhr;
            float ghi = (j ? a11 : a10) + bhi;
            float ghn = (j ? a21 : a20) + bhn;

            float xr = gi[gib + n]          + ghr + gf[gfb + n];
            float xi = gi[gib + Hh + n]     + ghi + gf[gfb + Hh + n];
            float resetgate = 1.0f / (1.0f + expf(-xr));
            float inputgate = 1.0f / (1.0f + expf(-xi));
            float newgate   = tanhf(gi[gib + 2 * Hh + n] + resetgate * ghn);

            float hprev = h_sm[(bg * 2 + j) * Hh + n];
            float hy = newgate + inputgate * (hprev - newgate);

            out[((size_t)b * Tt + t) * Hh + n] = hy;
            if (t == Tt - 1)
                out[(size_t)Bb * Tt * Hh + (size_t)b * Hh + n] = hy;
        }

        // ---- Grid-wide barrier (all 128 CTAs co-resident) ----
        __threadfence();          // make this step's out[] writes visible GPU-wide
        __syncthreads();          // all threads of CTA done (writes + h_sm reads)
        if (tid == 0) {
            unsigned int old  = atomicAdd(&g_bar, 1u);
            unsigned int need = (old / NBLK + 1u) * NBLK;
            while (true) {
                unsigned int cur;
                asm volatile("ld.acquire.gpu.u32 %0, [%1];"
                             : "=r"(cur) : "l"(&g_bar));
                if (cur >= need) break;
            }
            __threadfence();
        }
        __syncthreads();
    }
}

// ---------------------------------------------------------------------------
// Launch
// ---------------------------------------------------------------------------
extern "C" void kernel_launch(void* const* d_in, const int* in_sizes, int n_in,
                              void* d_out, int out_size)
{
    const float* feat0 = (const float*)d_in[0];   // [B,T,FS]
    const float* feat1 = (const float*)d_in[1];   // [B,T,IN]
    const float* W_ih  = (const float*)d_in[2];   // [3H, IN]
    const float* b_ih  = (const float*)d_in[3];   // [3H]
    const float* W_hh  = (const float*)d_in[4];   // [3H, H]
    const float* b_hh  = (const float*)d_in[5];   // [3H]
    const float* W_fh  = (const float*)d_in[6];   // [2H, FS]
    const float* b_fh  = (const float*)d_in[7];   // [2H]
    float* out = (float*)d_out;

    float *gi_ptr, *gf_ptr;
    cudaGetSymbolAddress((void**)&gi_ptr, g_gi);
    cudaGetSymbolAddress((void**)&gf_ptr, g_gf);

    // gi = feat1 @ W_ih^T + b_ih : M=8192, N=1536, K=2048
    {
        dim3 grid((3 * Hh) / 128, MROWS / 128);
        sgemm_bias_kernel<<<grid, 256>>>(feat1, W_ih, b_ih, gi_ptr,
                                         MROWS, 3 * Hh, INPS);
    }
    // gf = feat0 @ W_fh^T + b_fh : M=8192, N=1024, K=1536
    {
        dim3 grid((2 * Hh) / 128, MROWS / 128);
        sgemm_bias_kernel<<<grid, 256>>>(feat0, W_fh, b_fh, gf_ptr,
                                         MROWS, 2 * Hh, FS);
    }
    // Recurrence: single persistent kernel, 64 steps internally
    {
        const int smem_bytes = (3 * Hh * NC + BBB * Hh) * (int)sizeof(float); // 163840
        cudaFuncSetAttribute(gru_persistent_kernel,
                             cudaFuncAttributeMaxDynamicSharedMemorySize, smem_bytes);
        dim3 grid(Hh / NC, Bb / BBB);   // (32, 4) = 128 CTAs
        gru_persistent_kernel<<<grid, STEP_THREADS, smem_bytes>>>(
            gi_ptr, gf_ptr, W_hh, b_hh, out);
    }
}